// round 12
// baseline (speedup 1.0000x reference)
#include <cuda_runtime.h>
#include <cuda_fp16.h>
#include <math.h>

// Problem dims (fixed by dataset)
#define MAXN 50000
#define MAXE 850000   // 800000 edges + 50000 self loops
#define IN_DIM 256
#define H1DIM 128     // 8 heads * 16
#define HEADS1 8
#define H2DIM 64
#define NEG_SLOPE 0.2f

// ---------------- scratch (static device globals; no allocation) -------------
__device__ float  g_h1[MAXN * H1DIM];     // fp32 (for scores1)
__device__ __half g_h1h[MAXN * H1DIM];    // fp16 mirror (for agg1 gather)
__device__ float  g_s1src[MAXN * HEADS1];
__device__ float  g_s1dst[MAXN * HEADS1];
__device__ int    g_deg[MAXN];
__device__ int    g_rowptr[MAXN + 1];
__device__ int    g_cursor[MAXN];
__device__ int    g_esrc[MAXE];
__device__ float  g_out1[MAXN * H1DIM];
__device__ float  g_h2[MAXN * H2DIM];     // fp32 (for scores2)
__device__ __half g_h2h[MAXN * H2DIM];    // fp16 mirror (for agg2 gather)
__device__ float  g_s2src[MAXN];
__device__ float  g_s2dst[MAXN];
__device__ int    g_is64;

// ---------------- helpers -----------------------------------------------------
__device__ __forceinline__ int edge_at(const void* ei, size_t idx) {
    if (g_is64) return (int)((const long long*)ei)[idx];
    return ((const int*)ei)[idx];
}

__device__ __forceinline__ float to_tf32(float x) {
    float r;
    asm("cvt.rna.tf32.f32 %0, %1;" : "=f"(r) : "f"(x));
    return r;
}

__device__ __forceinline__ float lrelu(float v) {
    return (v > 0.f) ? v : NEG_SLOPE * v;
}

__device__ __forceinline__ void mma_tf32(float* d, const unsigned* a,
                                         unsigned b0, unsigned b1) {
    asm volatile(
        "mma.sync.aligned.m16n8k8.row.col.f32.tf32.tf32.f32 "
        "{%0,%1,%2,%3}, {%4,%5,%6,%7}, {%8,%9}, {%0,%1,%2,%3};"
        : "+f"(d[0]), "+f"(d[1]), "+f"(d[2]), "+f"(d[3])
        : "r"(a[0]), "r"(a[1]), "r"(a[2]), "r"(a[3]), "r"(b0), "r"(b1));
}

// ---------------- init: deg=1 everywhere + edge-dtype detect ------------------
__global__ void init_kernel(const int* __restrict__ ei32, int Nn) {
    int i = blockIdx.x * blockDim.x + threadIdx.x;
    if (i < Nn) g_deg[i] = 1;   // self loop pre-counted
    if (i == 0) {
        int all_zero = 1;
        for (int k = 0; k < 64; k++)
            if (ei32[2 * k + 1] != 0) { all_zero = 0; break; }
        g_is64 = all_zero;
    }
}

// ---------------- tf32 tensor-core GEMM body ----------------------------------
// Block tile 128 x BN; 256 threads. Writes fp32 C and fp16 mirror Ch.
// WHICH==0: A=arg(x), C=g_h1/g_h1h.  WHICH==1: A=g_out1, C=g_h2/g_h2h.
template <int BN, int WHICH>
__device__ __forceinline__ void gemm_body(const float* __restrict__ Aarg,
                                          const float* __restrict__ B,
                                          int M, int K, int bidx) {
    const float* __restrict__ A = (WHICH == 0) ? Aarg : (const float*)g_out1;
    float*  __restrict__ C  = (WHICH == 0) ? g_h1  : g_h2;
    __half* __restrict__ Ch = (WHICH == 0) ? g_h1h : g_h2h;

    constexpr int KB   = 32;
    constexpr int NW_N = BN / 64;
    constexpr int WM   = 128 / (8 / NW_N);
    constexpr int MAT  = WM / 16;
    constexpr int NAT  = 8;

    __shared__ float As[128][36];
    __shared__ float Bs[KB][BN + 4];

    const int tid  = threadIdx.x;
    const int wid  = tid >> 5;
    const int lane = tid & 31;
    const int wm   = (wid / NW_N) * WM;
    const int wn   = (wid % NW_N) * 64;
    const int bm   = bidx * 128;
    const int lq   = lane & 3;
    const int lg   = lane >> 2;

    float acc[MAT][NAT][4];
#pragma unroll
    for (int i = 0; i < MAT; i++)
#pragma unroll
        for (int j = 0; j < NAT; j++)
#pragma unroll
            for (int c = 0; c < 4; c++) acc[i][j][c] = 0.0f;

    for (int k0 = 0; k0 < K; k0 += KB) {
#pragma unroll
        for (int i = 0; i < 4; i++) {
            int idx = tid + i * 256;
            int row = idx >> 3;
            int kc  = (idx & 7) * 4;
            int gm  = bm + row;
            int gmc = (gm < M) ? gm : (M - 1);
            float4 v = *(const float4*)(A + (size_t)gmc * K + k0 + kc);
            if (gm >= M) v = make_float4(0.f, 0.f, 0.f, 0.f);
            v.x = to_tf32(v.x); v.y = to_tf32(v.y);
            v.z = to_tf32(v.z); v.w = to_tf32(v.w);
            *(float4*)&As[row][kc] = v;
        }
#pragma unroll
        for (int i = 0; i < (KB * BN) / (4 * 256); i++) {
            int idx = tid + i * 256;
            int kk  = idx / (BN / 4);
            int nc  = (idx % (BN / 4)) * 4;
            float4 v = *(const float4*)(B + (size_t)(k0 + kk) * BN + nc);
            v.x = to_tf32(v.x); v.y = to_tf32(v.y);
            v.z = to_tf32(v.z); v.w = to_tf32(v.w);
            *(float4*)&Bs[kk][nc] = v;
        }
        __syncthreads();
#pragma unroll
        for (int ks = 0; ks < KB; ks += 8) {
            unsigned a[MAT][4];
#pragma unroll
            for (int i = 0; i < MAT; i++) {
                int m0 = wm + i * 16;
                a[i][0] = __float_as_uint(As[m0 + lg][ks + lq]);
                a[i][1] = __float_as_uint(As[m0 + lg + 8][ks + lq]);
                a[i][2] = __float_as_uint(As[m0 + lg][ks + lq + 4]);
                a[i][3] = __float_as_uint(As[m0 + lg + 8][ks + lq + 4]);
            }
#pragma unroll
            for (int j = 0; j < NAT; j++) {
                unsigned b0 = __float_as_uint(Bs[ks + lq][wn + j * 8 + lg]);
                unsigned b1 = __float_as_uint(Bs[ks + lq + 4][wn + j * 8 + lg]);
#pragma unroll
                for (int i = 0; i < MAT; i++) mma_tf32(acc[i][j], a[i], b0, b1);
            }
        }
        __syncthreads();
    }
#pragma unroll
    for (int i = 0; i < MAT; i++) {
#pragma unroll
        for (int j = 0; j < NAT; j++) {
            int gm = bm + wm + i * 16 + lg;
            int n0 = wn + j * 8 + 2 * lq;
            if (gm < M) {
                *(float2*)(C + (size_t)gm * BN + n0) =
                    make_float2(acc[i][j][0], acc[i][j][1]);
                *(__half2*)(Ch + (size_t)gm * BN + n0) =
                    __floats2half2_rn(acc[i][j][0], acc[i][j][1]);
            }
            if (gm + 8 < M) {
                *(float2*)(C + (size_t)(gm + 8) * BN + n0) =
                    make_float2(acc[i][j][2], acc[i][j][3]);
                *(__half2*)(Ch + (size_t)(gm + 8) * BN + n0) =
                    __floats2half2_rn(acc[i][j][2], acc[i][j][3]);
            }
        }
    }
}

// ---------------- K1: gemm1 blocks || histo blocks ----------------------------
__global__ __launch_bounds__(256)
void k1_gemm1_histo(const float* __restrict__ x, const float* __restrict__ W1,
                    const void* __restrict__ ei, int M, int E, int nGemmBlocks) {
    if ((int)blockIdx.x < nGemmBlocks) {
        gemm_body<H1DIM, 0>(x, W1, M, IN_DIM, blockIdx.x);
    } else {
        int e = (blockIdx.x - nGemmBlocks) * 256 + threadIdx.x;
        if (e < E) atomicAdd(&g_deg[edge_at(ei, (size_t)E + e)], 1);
    }
}

// ---------------- scan (1 block) ----------------------------------------------
__global__ __launch_bounds__(1024)
void scan_kernel(int Nn) {
    __shared__ int sums[2048];
    int tid = threadIdx.x;
    int chunk = (Nn + 1023) >> 10;
    int b = tid * chunk;
    int e = min(b + chunk, Nn);
    int s = 0;
    for (int i = b; i < e; i++) s += g_deg[i];
    sums[tid] = 0;
    sums[1024 + tid] = s;
    __syncthreads();
    for (int off = 1; off < 1024; off <<= 1) {
        int v = sums[1024 + tid - off];
        __syncthreads();
        sums[1024 + tid] += v;
        __syncthreads();
    }
    int run = sums[1023 + tid];
    for (int i = b; i < e; i++) {
        g_rowptr[i] = run;
        g_cursor[i] = run;
        run += g_deg[i];
    }
    if (tid == 1023) g_rowptr[Nn] = sums[2047];
}

// ---------------- K2: scores1 blocks || scatter blocks -------------------------
__global__ __launch_bounds__(256)
void k2_scores1_scatter(const float* __restrict__ a1s, const float* __restrict__ a1d,
                        const void* __restrict__ ei, int Nn, int E, int nScoreBlocks) {
    if ((int)blockIdx.x < nScoreBlocks) {
        int idx = blockIdx.x * 256 + threadIdx.x;
        if (idx >= Nn * HEADS1) return;
        int n = idx >> 3, h = idx & 7;
        const float4* hp = (const float4*)(g_h1 + (size_t)n * H1DIM + h * 16);
        const float4* as = (const float4*)(a1s + h * 16);
        const float4* ad = (const float4*)(a1d + h * 16);
        float ss = 0.f, sd = 0.f;
#pragma unroll
        for (int q = 0; q < 4; q++) {
            float4 v = hp[q], s4 = as[q], d4 = ad[q];
            ss += v.x * s4.x + v.y * s4.y + v.z * s4.z + v.w * s4.w;
            sd += v.x * d4.x + v.y * d4.y + v.z * d4.z + v.w * d4.w;
        }
        g_s1src[idx] = ss;
        g_s1dst[idx] = sd;
    } else {
        int idx = (blockIdx.x - nScoreBlocks) * 256 + threadIdx.x;
        if (idx >= E + Nn) return;
        int src, dst;
        if (idx < E) {
            src = edge_at(ei, (size_t)idx);
            dst = edge_at(ei, (size_t)E + idx);
        } else {
            src = dst = idx - E;  // self loop
        }
        int pos = atomicAdd(&g_cursor[dst], 1);
        g_esrc[pos] = src;
    }
}

// ---------------- layer-1 softmax+agg (fp16 gather, 8x unroll) ----------------
__global__ __launch_bounds__(256)
void agg1_kernel(const float* __restrict__ b1, int Nn) {
    int warp = (blockIdx.x * blockDim.x + threadIdx.x) >> 5;
    int lane = threadIdx.x & 31;
    if (warp >= Nn) return;
    int beg = g_rowptr[warp], end = g_rowptr[warp + 1];
    const int head = lane >> 2;
    const float sdst = g_s1dst[(size_t)warp * HEADS1 + head];

    float4 acc = make_float4(0.f, 0.f, 0.f, 0.f);
    float s = 0.f;
    int j = beg;
    for (; j + 7 < end; j += 8) {
        int   idx[8];
        float w[8];
        uint2 u[8];
#pragma unroll
        for (int t = 0; t < 8; t++) idx[t] = g_esrc[j + t];
#pragma unroll
        for (int t = 0; t < 8; t++)
            u[t] = *(const uint2*)(g_h1h + (size_t)idx[t] * H1DIM + lane * 4);
#pragma unroll
        for (int t = 0; t < 8; t++)
            w[t] = __expf(lrelu(g_s1src[(size_t)idx[t] * HEADS1 + head] + sdst));
#pragma unroll
        for (int t = 0; t < 8; t++) {
            s += w[t];
            float2 p = __half22float2(*(__half2*)&u[t].x);
            float2 q = __half22float2(*(__half2*)&u[t].y);
            acc.x = fmaf(w[t], p.x, acc.x); acc.y = fmaf(w[t], p.y, acc.y);
            acc.z = fmaf(w[t], q.x, acc.z); acc.w = fmaf(w[t], q.y, acc.w);
        }
    }
    for (; j < end; ++j) {
        int i0 = g_esrc[j];
        float w0 = __expf(lrelu(g_s1src[(size_t)i0 * HEADS1 + head] + sdst));
        uint2 u0 = *(const uint2*)(g_h1h + (size_t)i0 * H1DIM + lane * 4);
        s += w0;
        float2 p = __half22float2(*(__half2*)&u0.x);
        float2 q = __half22float2(*(__half2*)&u0.y);
        acc.x = fmaf(w0, p.x, acc.x); acc.y = fmaf(w0, p.y, acc.y);
        acc.z = fmaf(w0, q.x, acc.z); acc.w = fmaf(w0, q.y, acc.w);
    }
    float inv = 1.0f / s;
    float4 bb = *(const float4*)(b1 + lane * 4);
    float4 o;
    o.x = acc.x * inv + bb.x;  o.y = acc.y * inv + bb.y;
    o.z = acc.z * inv + bb.z;  o.w = acc.w * inv + bb.w;
    o.x = (o.x > 0.f) ? o.x : (__expf(o.x) - 1.0f);
    o.y = (o.y > 0.f) ? o.y : (__expf(o.y) - 1.0f);
    o.z = (o.z > 0.f) ? o.z : (__expf(o.z) - 1.0f);
    o.w = (o.w > 0.f) ? o.w : (__expf(o.w) - 1.0f);
    *(float4*)(g_out1 + (size_t)warp * H1DIM + lane * 4) = o;
}

// ---------------- gemm2 (standalone) ------------------------------------------
__global__ __launch_bounds__(256)
void gemm2_kernel(const float* __restrict__ W2, int M) {
    gemm_body<H2DIM, 1>(nullptr, W2, M, H1DIM, blockIdx.x);
}

// ---------------- layer-2 scores (warp per node) -------------------------------
__global__ __launch_bounds__(256)
void scores2_kernel(const float* __restrict__ a2s, const float* __restrict__ a2d, int Nn) {
    int warp = (blockIdx.x * blockDim.x + threadIdx.x) >> 5;
    int lane = threadIdx.x & 31;
    if (warp >= Nn) return;
    const float2 v  = *(const float2*)(g_h2 + (size_t)warp * H2DIM + lane * 2);
    const float2 s2 = *(const float2*)(a2s + lane * 2);
    const float2 d2 = *(const float2*)(a2d + lane * 2);
    float ss = v.x * s2.x + v.y * s2.y;
    float sd = v.x * d2.x + v.y * d2.y;
#pragma unroll
    for (int o = 16; o > 0; o >>= 1) {
        ss += __shfl_xor_sync(0xFFFFFFFFu, ss, o);
        sd += __shfl_xor_sync(0xFFFFFFFFu, sd, o);
    }
    if (lane == 0) {
        g_s2src[warp] = ss;
        g_s2dst[warp] = sd;
    }
}

// ---------------- layer-2 softmax+agg (fp16 gather, 8x) + log_softmax ---------
__global__ __launch_bounds__(256)
void agg2_kernel(const float* __restrict__ b2, float* __restrict__ dout, int Nn) {
    int warp = (blockIdx.x * blockDim.x + threadIdx.x) >> 5;
    int lane = threadIdx.x & 31;
    if (warp >= Nn) return;
    int beg = g_rowptr[warp], end = g_rowptr[warp + 1];
    const float sdst = g_s2dst[warp];

    float a0 = 0.f, a1 = 0.f, s = 0.f;
    int j = beg;
    for (; j + 7 < end; j += 8) {
        int     idx[8];
        float   w[8];
        __half2 u[8];
#pragma unroll
        for (int t = 0; t < 8; t++) idx[t] = g_esrc[j + t];
#pragma unroll
        for (int t = 0; t < 8; t++)
            u[t] = *(const __half2*)(g_h2h + (size_t)idx[t] * H2DIM + lane * 2);
#pragma unroll
        for (int t = 0; t < 8; t++)
            w[t] = __expf(lrelu(g_s2src[idx[t]] + sdst));
#pragma unroll
        for (int t = 0; t < 8; t++) {
            s += w[t];
            float2 f = __half22float2(u[t]);
            a0 = fmaf(w[t], f.x, a0); a1 = fmaf(w[t], f.y, a1);
        }
    }
    for (; j < end; ++j) {
        int i0 = g_esrc[j];
        float w0 = __expf(lrelu(g_s2src[i0] + sdst));
        __half2 u0 = *(const __half2*)(g_h2h + (size_t)i0 * H2DIM + lane * 2);
        s += w0;
        float2 f = __half22float2(u0);
        a0 = fmaf(w0, f.x, a0); a1 = fmaf(w0, f.y, a1);
    }
    float inv = 1.0f / s;
    float2 bb = *(const float2*)(b2 + lane * 2);
    float o0 = a0 * inv + bb.x;
    float o1 = a1 * inv + bb.y;

    // fused log_softmax over the node's 64 outputs
    float mx = fmaxf(o0, o1);
#pragma unroll
    for (int o = 16; o > 0; o >>= 1) mx = fmaxf(mx, __shfl_xor_sync(0xFFFFFFFFu, mx, o));
    float se = __expf(o0 - mx) + __expf(o1 - mx);
#pragma unroll
    for (int o = 16; o > 0; o >>= 1) se += __shfl_xor_sync(0xFFFFFFFFu, se, o);
    float lse = __logf(se);
    float2 r;  r.x = o0 - mx - lse;  r.y = o1 - mx - lse;
    *(float2*)(dout + (size_t)warp * H2DIM + lane * 2) = r;
}

// ---------------- launch (pure kernel launches, default stream) --------------
extern "C" void kernel_launch(void* const* d_in, const int* in_sizes, int n_in,
                              void* d_out, int out_size) {
    const float* x   = (const float*)d_in[0];
    const void*  ei  = d_in[1];
    const float* W1  = (const float*)d_in[2];
    const float* a1s = (const float*)d_in[3];
    const float* a1d = (const float*)d_in[4];
    const float* b1  = (const float*)d_in[5];
    const float* W2  = (const float*)d_in[6];
    const float* a2s = (const float*)d_in[7];
    const float* a2d = (const float*)d_in[8];
    const float* b2  = (const float*)d_in[9];
    float*       out = (float*)d_out;

    const int Nn   = in_sizes[0] / IN_DIM;  // 50000
    const int E    = in_sizes[1] / 2;       // 800000
    const int Etot = E + Nn;

    const int nG1 = (Nn + 127) / 128;             // gemm1 blocks
    const int nH  = (E + 255) / 256;              // histo blocks
    const int nS1 = (Nn * HEADS1 + 255) / 256;    // scores1 blocks
    const int nSc = (Etot + 255) / 256;           // scatter blocks

    init_kernel<<<(Nn + 255) / 256, 256>>>((const int*)ei, Nn);
    k1_gemm1_histo<<<nG1 + nH, 256>>>(x, W1, ei, Nn, E, nG1);
    scan_kernel<<<1, 1024>>>(Nn);
    k2_scores1_scatter<<<nS1 + nSc, 256>>>(a1s, a1d, ei, Nn, E, nS1);
    agg1_kernel<<<(Nn + 7) / 8, 256>>>(b1, Nn);

    gemm2_kernel<<<(Nn + 127) / 128, 256>>>(W2, Nn);
    scores2_kernel<<<(Nn + 7) / 8, 256>>>(a2s, a2d, Nn);
    agg2_kernel<<<(Nn + 7) / 8, 256>>>(b2, out, Nn);
}

// round 13
// speedup vs baseline: 1.4432x; 1.4432x over previous
#include <cuda_runtime.h>
#include <cuda_fp16.h>
#include <math.h>

// Problem dims (fixed by dataset)
#define MAXN 50000
#define MAXE 850000   // 800000 edges + 50000 self loops
#define IN_DIM 256
#define H1DIM 128     // 8 heads * 16
#define HEADS1 8
#define H2DIM 64
#define NEG_SLOPE 0.2f
#define SCAN_B 1024
#define MAX_SB 64     // max scan blocks (ceil(MAXN/1024)=49)

// ---------------- scratch (static device globals; no allocation) -------------
__device__ float  g_h1[MAXN * H1DIM];     // fp32 (for scores1)
__device__ __half g_h1h[MAXN * H1DIM];    // fp16 mirror (for agg1 gather)
__device__ float  g_s1src[MAXN * HEADS1];
__device__ float  g_s1dst[MAXN * HEADS1];
__device__ int    g_deg[MAXN];
__device__ int    g_rowptr[MAXN + 1];
__device__ int    g_cursor[MAXN];
__device__ int    g_esrc[MAXE];
__device__ float  g_out1[MAXN * H1DIM];
__device__ float  g_h2[MAXN * H2DIM];     // fp32 (for scores2)
__device__ __half g_h2h[MAXN * H2DIM];    // fp16 mirror (for agg2 gather)
__device__ float  g_s2src[MAXN];
__device__ float  g_s2dst[MAXN];
__device__ int    g_is64;
__device__ int    g_bsum[MAX_SB];
__device__ int    g_boff[MAX_SB];

// ---------------- helpers -----------------------------------------------------
__device__ __forceinline__ int edge_at(const void* ei, size_t idx) {
    if (g_is64) return (int)((const long long*)ei)[idx];
    return ((const int*)ei)[idx];
}

__device__ __forceinline__ float to_tf32(float x) {
    float r;
    asm("cvt.rna.tf32.f32 %0, %1;" : "=f"(r) : "f"(x));
    return r;
}

__device__ __forceinline__ float lrelu(float v) {
    return (v > 0.f) ? v : NEG_SLOPE * v;
}

__device__ __forceinline__ void mma_tf32(float* d, const unsigned* a,
                                         unsigned b0, unsigned b1) {
    asm volatile(
        "mma.sync.aligned.m16n8k8.row.col.f32.tf32.tf32.f32 "
        "{%0,%1,%2,%3}, {%4,%5,%6,%7}, {%8,%9}, {%0,%1,%2,%3};"
        : "+f"(d[0]), "+f"(d[1]), "+f"(d[2]), "+f"(d[3])
        : "r"(a[0]), "r"(a[1]), "r"(a[2]), "r"(a[3]), "r"(b0), "r"(b1));
}

// ---------------- init: deg=1 everywhere + edge-dtype detect ------------------
__global__ void init_kernel(const int* __restrict__ ei32, int Nn) {
    int i = blockIdx.x * blockDim.x + threadIdx.x;
    if (i < Nn) g_deg[i] = 1;   // self loop pre-counted
    if (i == 0) {
        int all_zero = 1;
        for (int k = 0; k < 64; k++)
            if (ei32[2 * k + 1] != 0) { all_zero = 0; break; }
        g_is64 = all_zero;
    }
}

// ---------------- tf32 tensor-core GEMM body ----------------------------------
template <int BN, int WHICH>
__device__ __forceinline__ void gemm_body(const float* __restrict__ Aarg,
                                          const float* __restrict__ B,
                                          int M, int K, int bidx) {
    const float* __restrict__ A = (WHICH == 0) ? Aarg : (const float*)g_out1;
    float*  __restrict__ C  = (WHICH == 0) ? g_h1  : g_h2;
    __half* __restrict__ Ch = (WHICH == 0) ? g_h1h : g_h2h;

    constexpr int KB   = 32;
    constexpr int NW_N = BN / 64;
    constexpr int WM   = 128 / (8 / NW_N);
    constexpr int MAT  = WM / 16;
    constexpr int NAT  = 8;

    __shared__ float As[128][36];
    __shared__ float Bs[KB][BN + 4];

    const int tid  = threadIdx.x;
    const int wid  = tid >> 5;
    const int lane = tid & 31;
    const int wm   = (wid / NW_N) * WM;
    const int wn   = (wid % NW_N) * 64;
    const int bm   = bidx * 128;
    const int lq   = lane & 3;
    const int lg   = lane >> 2;

    float acc[MAT][NAT][4];
#pragma unroll
    for (int i = 0; i < MAT; i++)
#pragma unroll
        for (int j = 0; j < NAT; j++)
#pragma unroll
            for (int c = 0; c < 4; c++) acc[i][j][c] = 0.0f;

    for (int k0 = 0; k0 < K; k0 += KB) {
#pragma unroll
        for (int i = 0; i < 4; i++) {
            int idx = tid + i * 256;
            int row = idx >> 3;
            int kc  = (idx & 7) * 4;
            int gm  = bm + row;
            int gmc = (gm < M) ? gm : (M - 1);
            float4 v = *(const float4*)(A + (size_t)gmc * K + k0 + kc);
            if (gm >= M) v = make_float4(0.f, 0.f, 0.f, 0.f);
            v.x = to_tf32(v.x); v.y = to_tf32(v.y);
            v.z = to_tf32(v.z); v.w = to_tf32(v.w);
            *(float4*)&As[row][kc] = v;
        }
#pragma unroll
        for (int i = 0; i < (KB * BN) / (4 * 256); i++) {
            int idx = tid + i * 256;
            int kk  = idx / (BN / 4);
            int nc  = (idx % (BN / 4)) * 4;
            float4 v = *(const float4*)(B + (size_t)(k0 + kk) * BN + nc);
            v.x = to_tf32(v.x); v.y = to_tf32(v.y);
            v.z = to_tf32(v.z); v.w = to_tf32(v.w);
            *(float4*)&Bs[kk][nc] = v;
        }
        __syncthreads();
#pragma unroll
        for (int ks = 0; ks < KB; ks += 8) {
            unsigned a[MAT][4];
#pragma unroll
            for (int i = 0; i < MAT; i++) {
                int m0 = wm + i * 16;
                a[i][0] = __float_as_uint(As[m0 + lg][ks + lq]);
                a[i][1] = __float_as_uint(As[m0 + lg + 8][ks + lq]);
                a[i][2] = __float_as_uint(As[m0 + lg][ks + lq + 4]);
                a[i][3] = __float_as_uint(As[m0 + lg + 8][ks + lq + 4]);
            }
#pragma unroll
            for (int j = 0; j < NAT; j++) {
                unsigned b0 = __float_as_uint(Bs[ks + lq][wn + j * 8 + lg]);
                unsigned b1 = __float_as_uint(Bs[ks + lq + 4][wn + j * 8 + lg]);
#pragma unroll
                for (int i = 0; i < MAT; i++) mma_tf32(acc[i][j], a[i], b0, b1);
            }
        }
        __syncthreads();
    }
#pragma unroll
    for (int i = 0; i < MAT; i++) {
#pragma unroll
        for (int j = 0; j < NAT; j++) {
            int gm = bm + wm + i * 16 + lg;
            int n0 = wn + j * 8 + 2 * lq;
            if (gm < M) {
                *(float2*)(C + (size_t)gm * BN + n0) =
                    make_float2(acc[i][j][0], acc[i][j][1]);
                *(__half2*)(Ch + (size_t)gm * BN + n0) =
                    __floats2half2_rn(acc[i][j][0], acc[i][j][1]);
            }
            if (gm + 8 < M) {
                *(float2*)(C + (size_t)(gm + 8) * BN + n0) =
                    make_float2(acc[i][j][2], acc[i][j][3]);
                *(__half2*)(Ch + (size_t)(gm + 8) * BN + n0) =
                    __floats2half2_rn(acc[i][j][2], acc[i][j][3]);
            }
        }
    }
}

// ---------------- K1: gemm1 blocks || histo blocks ----------------------------
__global__ __launch_bounds__(256)
void k1_gemm1_histo(const float* __restrict__ x, const float* __restrict__ W1,
                    const void* __restrict__ ei, int M, int E, int nGemmBlocks) {
    if ((int)blockIdx.x < nGemmBlocks) {
        gemm_body<H1DIM, 0>(x, W1, M, IN_DIM, blockIdx.x);
    } else {
        int e = (blockIdx.x - nGemmBlocks) * 256 + threadIdx.x;
        if (e < E) atomicAdd(&g_deg[edge_at(ei, (size_t)E + e)], 1);
    }
}

// ---------------- coalesced 3-phase scan ---------------------------------------
// Phase 1: per-block sums (coalesced reads)
__global__ __launch_bounds__(SCAN_B)
void blocksum_kernel(int Nn) {
    __shared__ int wsum[SCAN_B / 32];
    int i = blockIdx.x * SCAN_B + threadIdx.x;
    int v = (i < Nn) ? g_deg[i] : 0;
#pragma unroll
    for (int o = 16; o > 0; o >>= 1) v += __shfl_xor_sync(0xFFFFFFFFu, v, o);
    int lane = threadIdx.x & 31, w = threadIdx.x >> 5;
    if (lane == 0) wsum[w] = v;
    __syncthreads();
    if (w == 0) {
        int s = (lane < SCAN_B / 32) ? wsum[lane] : 0;
#pragma unroll
        for (int o = 16; o > 0; o >>= 1) s += __shfl_xor_sync(0xFFFFFFFFu, s, o);
        if (lane == 0) g_bsum[blockIdx.x] = s;
    }
}

// Phase 2: exclusive scan of block sums (1 block, 64 threads = 2 warps)
__global__ __launch_bounds__(64)
void bscan_kernel(int nSB, int Nn) {
    __shared__ int wtot[2];
    int t = threadIdx.x;
    int v = (t < nSB) ? g_bsum[t] : 0;
    int lane = t & 31, w = t >> 5;
    int incl = v;
#pragma unroll
    for (int o = 1; o < 32; o <<= 1) {
        int u = __shfl_up_sync(0xFFFFFFFFu, incl, o);
        if (lane >= o) incl += u;
    }
    if (lane == 31) wtot[w] = incl;
    __syncthreads();
    int base = (w == 1) ? wtot[0] : 0;
    incl += base;
    if (t < nSB) g_boff[t] = incl - v;   // exclusive prefix
    if (t == nSB - 1) g_rowptr[Nn] = incl;
}

// Phase 3: per-block shared-mem scan + offset, coalesced writes
__global__ __launch_bounds__(SCAN_B)
void final_scan_kernel(int Nn) {
    __shared__ int sums[2 * SCAN_B];
    int tid = threadIdx.x;
    int i = blockIdx.x * SCAN_B + tid;
    int v = (i < Nn) ? g_deg[i] : 0;
    sums[tid] = 0;
    sums[SCAN_B + tid] = v;
    __syncthreads();
    for (int off = 1; off < SCAN_B; off <<= 1) {
        int u = sums[SCAN_B + tid - off];
        __syncthreads();
        sums[SCAN_B + tid] += u;
        __syncthreads();
    }
    int excl = sums[SCAN_B - 1 + tid];       // exclusive within block
    int pref = g_boff[blockIdx.x] + excl;
    if (i < Nn) {
        g_rowptr[i] = pref;
        g_cursor[i] = pref;
    }
}

// ---------------- K2: scores1 blocks || scatter blocks -------------------------
__global__ __launch_bounds__(256)
void k2_scores1_scatter(const float* __restrict__ a1s, const float* __restrict__ a1d,
                        const void* __restrict__ ei, int Nn, int E, int nScoreBlocks) {
    if ((int)blockIdx.x < nScoreBlocks) {
        int idx = blockIdx.x * 256 + threadIdx.x;
        if (idx >= Nn * HEADS1) return;
        int n = idx >> 3, h = idx & 7;
        const float4* hp = (const float4*)(g_h1 + (size_t)n * H1DIM + h * 16);
        const float4* as = (const float4*)(a1s + h * 16);
        const float4* ad = (const float4*)(a1d + h * 16);
        float ss = 0.f, sd = 0.f;
#pragma unroll
        for (int q = 0; q < 4; q++) {
            float4 v = hp[q], s4 = as[q], d4 = ad[q];
            ss += v.x * s4.x + v.y * s4.y + v.z * s4.z + v.w * s4.w;
            sd += v.x * d4.x + v.y * d4.y + v.z * d4.z + v.w * d4.w;
        }
        g_s1src[idx] = ss;
        g_s1dst[idx] = sd;
    } else {
        int idx = (blockIdx.x - nScoreBlocks) * 256 + threadIdx.x;
        if (idx >= E + Nn) return;
        int src, dst;
        if (idx < E) {
            src = edge_at(ei, (size_t)idx);
            dst = edge_at(ei, (size_t)E + idx);
        } else {
            src = dst = idx - E;  // self loop
        }
        int pos = atomicAdd(&g_cursor[dst], 1);
        g_esrc[pos] = src;
    }
}

// ---------------- layer-1 softmax+agg (fp16 gather, 8x unroll) ----------------
__global__ __launch_bounds__(256)
void agg1_kernel(const float* __restrict__ b1, int Nn) {
    int warp = (blockIdx.x * blockDim.x + threadIdx.x) >> 5;
    int lane = threadIdx.x & 31;
    if (warp >= Nn) return;
    int beg = g_rowptr[warp], end = g_rowptr[warp + 1];
    const int head = lane >> 2;
    const float sdst = g_s1dst[(size_t)warp * HEADS1 + head];

    float4 acc = make_float4(0.f, 0.f, 0.f, 0.f);
    float s = 0.f;
    int j = beg;
    for (; j + 7 < end; j += 8) {
        int   idx[8];
        float w[8];
        uint2 u[8];
#pragma unroll
        for (int t = 0; t < 8; t++) idx[t] = g_esrc[j + t];
#pragma unroll
        for (int t = 0; t < 8; t++)
            u[t] = *(const uint2*)(g_h1h + (size_t)idx[t] * H1DIM + lane * 4);
#pragma unroll
        for (int t = 0; t < 8; t++)
            w[t] = __expf(lrelu(g_s1src[(size_t)idx[t] * HEADS1 + head] + sdst));
#pragma unroll
        for (int t = 0; t < 8; t++) {
            s += w[t];
            float2 p = __half22float2(*(__half2*)&u[t].x);
            float2 q = __half22float2(*(__half2*)&u[t].y);
            acc.x = fmaf(w[t], p.x, acc.x); acc.y = fmaf(w[t], p.y, acc.y);
            acc.z = fmaf(w[t], q.x, acc.z); acc.w = fmaf(w[t], q.y, acc.w);
        }
    }
    for (; j < end; ++j) {
        int i0 = g_esrc[j];
        float w0 = __expf(lrelu(g_s1src[(size_t)i0 * HEADS1 + head] + sdst));
        uint2 u0 = *(const uint2*)(g_h1h + (size_t)i0 * H1DIM + lane * 4);
        s += w0;
        float2 p = __half22float2(*(__half2*)&u0.x);
        float2 q = __half22float2(*(__half2*)&u0.y);
        acc.x = fmaf(w0, p.x, acc.x); acc.y = fmaf(w0, p.y, acc.y);
        acc.z = fmaf(w0, q.x, acc.z); acc.w = fmaf(w0, q.y, acc.w);
    }
    float inv = 1.0f / s;
    float4 bb = *(const float4*)(b1 + lane * 4);
    float4 o;
    o.x = acc.x * inv + bb.x;  o.y = acc.y * inv + bb.y;
    o.z = acc.z * inv + bb.z;  o.w = acc.w * inv + bb.w;
    o.x = (o.x > 0.f) ? o.x : (__expf(o.x) - 1.0f);
    o.y = (o.y > 0.f) ? o.y : (__expf(o.y) - 1.0f);
    o.z = (o.z > 0.f) ? o.z : (__expf(o.z) - 1.0f);
    o.w = (o.w > 0.f) ? o.w : (__expf(o.w) - 1.0f);
    *(float4*)(g_out1 + (size_t)warp * H1DIM + lane * 4) = o;
}

// ---------------- gemm2 (standalone) ------------------------------------------
__global__ __launch_bounds__(256)
void gemm2_kernel(const float* __restrict__ W2, int M) {
    gemm_body<H2DIM, 1>(nullptr, W2, M, H1DIM, blockIdx.x);
}

// ---------------- layer-2 scores (warp per node) -------------------------------
__global__ __launch_bounds__(256)
void scores2_kernel(const float* __restrict__ a2s, const float* __restrict__ a2d, int Nn) {
    int warp = (blockIdx.x * blockDim.x + threadIdx.x) >> 5;
    int lane = threadIdx.x & 31;
    if (warp >= Nn) return;
    const float2 v  = *(const float2*)(g_h2 + (size_t)warp * H2DIM + lane * 2);
    const float2 s2 = *(const float2*)(a2s + lane * 2);
    const float2 d2 = *(const float2*)(a2d + lane * 2);
    float ss = v.x * s2.x + v.y * s2.y;
    float sd = v.x * d2.x + v.y * d2.y;
#pragma unroll
    for (int o = 16; o > 0; o >>= 1) {
        ss += __shfl_xor_sync(0xFFFFFFFFu, ss, o);
        sd += __shfl_xor_sync(0xFFFFFFFFu, sd, o);
    }
    if (lane == 0) {
        g_s2src[warp] = ss;
        g_s2dst[warp] = sd;
    }
}

// ---------------- layer-2 softmax+agg (fp16 gather, 8x) + log_softmax ---------
__global__ __launch_bounds__(256)
void agg2_kernel(const float* __restrict__ b2, float* __restrict__ dout, int Nn) {
    int warp = (blockIdx.x * blockDim.x + threadIdx.x) >> 5;
    int lane = threadIdx.x & 31;
    if (warp >= Nn) return;
    int beg = g_rowptr[warp], end = g_rowptr[warp + 1];
    const float sdst = g_s2dst[warp];

    float a0 = 0.f, a1 = 0.f, s = 0.f;
    int j = beg;
    for (; j + 7 < end; j += 8) {
        int     idx[8];
        float   w[8];
        __half2 u[8];
#pragma unroll
        for (int t = 0; t < 8; t++) idx[t] = g_esrc[j + t];
#pragma unroll
        for (int t = 0; t < 8; t++)
            u[t] = *(const __half2*)(g_h2h + (size_t)idx[t] * H2DIM + lane * 2);
#pragma unroll
        for (int t = 0; t < 8; t++)
            w[t] = __expf(lrelu(g_s2src[idx[t]] + sdst));
#pragma unroll
        for (int t = 0; t < 8; t++) {
            s += w[t];
            float2 f = __half22float2(u[t]);
            a0 = fmaf(w[t], f.x, a0); a1 = fmaf(w[t], f.y, a1);
        }
    }
    for (; j < end; ++j) {
        int i0 = g_esrc[j];
        float w0 = __expf(lrelu(g_s2src[i0] + sdst));
        __half2 u0 = *(const __half2*)(g_h2h + (size_t)i0 * H2DIM + lane * 2);
        s += w0;
        float2 f = __half22float2(u0);
        a0 = fmaf(w0, f.x, a0); a1 = fmaf(w0, f.y, a1);
    }
    float inv = 1.0f / s;
    float2 bb = *(const float2*)(b2 + lane * 2);
    float o0 = a0 * inv + bb.x;
    float o1 = a1 * inv + bb.y;

    float mx = fmaxf(o0, o1);
#pragma unroll
    for (int o = 16; o > 0; o >>= 1) mx = fmaxf(mx, __shfl_xor_sync(0xFFFFFFFFu, mx, o));
    float se = __expf(o0 - mx) + __expf(o1 - mx);
#pragma unroll
    for (int o = 16; o > 0; o >>= 1) se += __shfl_xor_sync(0xFFFFFFFFu, se, o);
    float lse = __logf(se);
    float2 r;  r.x = o0 - mx - lse;  r.y = o1 - mx - lse;
    *(float2*)(dout + (size_t)warp * H2DIM + lane * 2) = r;
}

// ---------------- launch (pure kernel launches, default stream) --------------
extern "C" void kernel_launch(void* const* d_in, const int* in_sizes, int n_in,
                              void* d_out, int out_size) {
    const float* x   = (const float*)d_in[0];
    const void*  ei  = d_in[1];
    const float* W1  = (const float*)d_in[2];
    const float* a1s = (const float*)d_in[3];
    const float* a1d = (const float*)d_in[4];
    const float* b1  = (const float*)d_in[5];
    const float* W2  = (const float*)d_in[6];
    const float* a2s = (const float*)d_in[7];
    const float* a2d = (const float*)d_in[8];
    const float* b2  = (const float*)d_in[9];
    float*       out = (float*)d_out;

    const int Nn   = in_sizes[0] / IN_DIM;  // 50000
    const int E    = in_sizes[1] / 2;       // 800000
    const int Etot = E + Nn;

    const int nG1 = (Nn + 127) / 128;             // gemm1 blocks
    const int nH  = (E + 255) / 256;              // histo blocks
    const int nS1 = (Nn * HEADS1 + 255) / 256;    // scores1 blocks
    const int nSc = (Etot + 255) / 256;           // scatter blocks
    const int nSB = (Nn + SCAN_B - 1) / SCAN_B;   // scan blocks (49)

    init_kernel<<<(Nn + 255) / 256, 256>>>((const int*)ei, Nn);
    k1_gemm1_histo<<<nG1 + nH, 256>>>(x, W1, ei, Nn, E, nG1);
    blocksum_kernel<<<nSB, SCAN_B>>>(Nn);
    bscan_kernel<<<1, 64>>>(nSB, Nn);
    final_scan_kernel<<<nSB, SCAN_B>>>(Nn);
    k2_scores1_scatter<<<nS1 + nSc, 256>>>(a1s, a1d, ei, Nn, E, nS1);
    agg1_kernel<<<(Nn + 7) / 8, 256>>>(b1, Nn);

    gemm2_kernel<<<(Nn + 127) / 128, 256>>>(W2, Nn);
    scores2_kernel<<<(Nn + 7) / 8, 256>>>(a2s, a2d, Nn);
    agg2_kernel<<<(Nn + 7) / 8, 256>>>(b2, out, Nn);
}

// round 14
// speedup vs baseline: 1.4677x; 1.0170x over previous
#include <cuda_runtime.h>
#include <cuda_fp16.h>
#include <math.h>

// Problem dims (fixed by dataset)
#define MAXN 50000
#define MAXE 850000   // 800000 edges + 50000 self loops
#define IN_DIM 256
#define H1DIM 128     // 8 heads * 16
#define HEADS1 8
#define H2DIM 64
#define NEG_SLOPE 0.2f
#define SCAN_B 1024
#define MAX_SB 64     // max scan blocks (ceil(MAXN/1024)=49)

// ---------------- scratch (static device globals; no allocation) -------------
__device__ float  g_h1[MAXN * H1DIM];     // fp32 (for scores1)
__device__ __half g_h1h[MAXN * H1DIM];    // fp16 mirror (for agg1 gather)
__device__ float  g_s1src[MAXN * HEADS1];
__device__ float  g_s1dst[MAXN * HEADS1];
__device__ int    g_deg[MAXN];
__device__ int    g_rowptr[MAXN + 1];
__device__ int    g_cursor[MAXN];
__device__ int    g_esrc[MAXE];
__device__ float  g_out1[MAXN * H1DIM];
__device__ float  g_h2[MAXN * H2DIM];     // fp32 (for scores2)
__device__ __half g_h2h[MAXN * H2DIM];    // fp16 mirror (for agg2 gather)
__device__ float  g_s2src[MAXN];
__device__ float  g_s2dst[MAXN];
__device__ int    g_is64;
__device__ int    g_bsum[MAX_SB];

// ---------------- helpers -----------------------------------------------------
__device__ __forceinline__ int edge_at(const void* ei, size_t idx) {
    if (g_is64) return (int)((const long long*)ei)[idx];
    return ((const int*)ei)[idx];
}

__device__ __forceinline__ float to_tf32(float x) {
    float r;
    asm("cvt.rna.tf32.f32 %0, %1;" : "=f"(r) : "f"(x));
    return r;
}

__device__ __forceinline__ float lrelu(float v) {
    return (v > 0.f) ? v : NEG_SLOPE * v;
}

__device__ __forceinline__ void mma_tf32(float* d, const unsigned* a,
                                         unsigned b0, unsigned b1) {
    asm volatile(
        "mma.sync.aligned.m16n8k8.row.col.f32.tf32.tf32.f32 "
        "{%0,%1,%2,%3}, {%4,%5,%6,%7}, {%8,%9}, {%0,%1,%2,%3};"
        : "+f"(d[0]), "+f"(d[1]), "+f"(d[2]), "+f"(d[3])
        : "r"(a[0]), "r"(a[1]), "r"(a[2]), "r"(a[3]), "r"(b0), "r"(b1));
}

// ---------------- init: deg=1 everywhere + edge-dtype detect ------------------
__global__ void init_kernel(const int* __restrict__ ei32, int Nn) {
    int i = blockIdx.x * blockDim.x + threadIdx.x;
    if (i < Nn) g_deg[i] = 1;   // self loop pre-counted
    if (i == 0) {
        int all_zero = 1;
        for (int k = 0; k < 64; k++)
            if (ei32[2 * k + 1] != 0) { all_zero = 0; break; }
        g_is64 = all_zero;
    }
}

// ---------------- tf32 tensor-core GEMM body ----------------------------------
template <int BN, int WHICH>
__device__ __forceinline__ void gemm_body(const float* __restrict__ Aarg,
                                          const float* __restrict__ B,
                                          int M, int K, int bidx) {
    const float* __restrict__ A = (WHICH == 0) ? Aarg : (const float*)g_out1;
    float*  __restrict__ C  = (WHICH == 0) ? g_h1  : g_h2;
    __half* __restrict__ Ch = (WHICH == 0) ? g_h1h : g_h2h;

    constexpr int KB   = 32;
    constexpr int NW_N = BN / 64;
    constexpr int WM   = 128 / (8 / NW_N);
    constexpr int MAT  = WM / 16;
    constexpr int NAT  = 8;

    __shared__ float As[128][36];
    __shared__ float Bs[KB][BN + 4];

    const int tid  = threadIdx.x;
    const int wid  = tid >> 5;
    const int lane = tid & 31;
    const int wm   = (wid / NW_N) * WM;
    const int wn   = (wid % NW_N) * 64;
    const int bm   = bidx * 128;
    const int lq   = lane & 3;
    const int lg   = lane >> 2;

    float acc[MAT][NAT][4];
#pragma unroll
    for (int i = 0; i < MAT; i++)
#pragma unroll
        for (int j = 0; j < NAT; j++)
#pragma unroll
            for (int c = 0; c < 4; c++) acc[i][j][c] = 0.0f;

    for (int k0 = 0; k0 < K; k0 += KB) {
#pragma unroll
        for (int i = 0; i < 4; i++) {
            int idx = tid + i * 256;
            int row = idx >> 3;
            int kc  = (idx & 7) * 4;
            int gm  = bm + row;
            int gmc = (gm < M) ? gm : (M - 1);
            float4 v = *(const float4*)(A + (size_t)gmc * K + k0 + kc);
            if (gm >= M) v = make_float4(0.f, 0.f, 0.f, 0.f);
            v.x = to_tf32(v.x); v.y = to_tf32(v.y);
            v.z = to_tf32(v.z); v.w = to_tf32(v.w);
            *(float4*)&As[row][kc] = v;
        }
#pragma unroll
        for (int i = 0; i < (KB * BN) / (4 * 256); i++) {
            int idx = tid + i * 256;
            int kk  = idx / (BN / 4);
            int nc  = (idx % (BN / 4)) * 4;
            float4 v = *(const float4*)(B + (size_t)(k0 + kk) * BN + nc);
            v.x = to_tf32(v.x); v.y = to_tf32(v.y);
            v.z = to_tf32(v.z); v.w = to_tf32(v.w);
            *(float4*)&Bs[kk][nc] = v;
        }
        __syncthreads();
#pragma unroll
        for (int ks = 0; ks < KB; ks += 8) {
            unsigned a[MAT][4];
#pragma unroll
            for (int i = 0; i < MAT; i++) {
                int m0 = wm + i * 16;
                a[i][0] = __float_as_uint(As[m0 + lg][ks + lq]);
                a[i][1] = __float_as_uint(As[m0 + lg + 8][ks + lq]);
                a[i][2] = __float_as_uint(As[m0 + lg][ks + lq + 4]);
                a[i][3] = __float_as_uint(As[m0 + lg + 8][ks + lq + 4]);
            }
#pragma unroll
            for (int j = 0; j < NAT; j++) {
                unsigned b0 = __float_as_uint(Bs[ks + lq][wn + j * 8 + lg]);
                unsigned b1 = __float_as_uint(Bs[ks + lq + 4][wn + j * 8 + lg]);
#pragma unroll
                for (int i = 0; i < MAT; i++) mma_tf32(acc[i][j], a[i], b0, b1);
            }
        }
        __syncthreads();
    }
#pragma unroll
    for (int i = 0; i < MAT; i++) {
#pragma unroll
        for (int j = 0; j < NAT; j++) {
            int gm = bm + wm + i * 16 + lg;
            int n0 = wn + j * 8 + 2 * lq;
            if (gm < M) {
                *(float2*)(C + (size_t)gm * BN + n0) =
                    make_float2(acc[i][j][0], acc[i][j][1]);
                *(__half2*)(Ch + (size_t)gm * BN + n0) =
                    __floats2half2_rn(acc[i][j][0], acc[i][j][1]);
            }
            if (gm + 8 < M) {
                *(float2*)(C + (size_t)(gm + 8) * BN + n0) =
                    make_float2(acc[i][j][2], acc[i][j][3]);
                *(__half2*)(Ch + (size_t)(gm + 8) * BN + n0) =
                    __floats2half2_rn(acc[i][j][2], acc[i][j][3]);
            }
        }
    }
}

// ---------------- K1: gemm1 blocks || histo blocks ----------------------------
__global__ __launch_bounds__(256)
void k1_gemm1_histo(const float* __restrict__ x, const float* __restrict__ W1,
                    const void* __restrict__ ei, int M, int E, int nGemmBlocks) {
    if ((int)blockIdx.x < nGemmBlocks) {
        gemm_body<H1DIM, 0>(x, W1, M, IN_DIM, blockIdx.x);
    } else {
        int e = (blockIdx.x - nGemmBlocks) * 256 + threadIdx.x;
        if (e < E) atomicAdd(&g_deg[edge_at(ei, (size_t)E + e)], 1);
    }
}

// ---------------- coalesced 2-phase scan ---------------------------------------
// Phase 1: per-block sums (coalesced reads)
__global__ __launch_bounds__(SCAN_B)
void blocksum_kernel(int Nn) {
    __shared__ int wsum[SCAN_B / 32];
    int i = blockIdx.x * SCAN_B + threadIdx.x;
    int v = (i < Nn) ? g_deg[i] : 0;
#pragma unroll
    for (int o = 16; o > 0; o >>= 1) v += __shfl_xor_sync(0xFFFFFFFFu, v, o);
    int lane = threadIdx.x & 31, w = threadIdx.x >> 5;
    if (lane == 0) wsum[w] = v;
    __syncthreads();
    if (w == 0) {
        int s = (lane < SCAN_B / 32) ? wsum[lane] : 0;
#pragma unroll
        for (int o = 16; o > 0; o >>= 1) s += __shfl_xor_sync(0xFFFFFFFFu, s, o);
        if (lane == 0) g_bsum[blockIdx.x] = s;
    }
}

// Phase 2: per-block scan; each block computes its OWN offset via a masked
// warp reduction over the <=48 preceding block sums (no separate bscan launch).
__global__ __launch_bounds__(SCAN_B)
void final_scan_kernel(int Nn, int nSB) {
    __shared__ int sums[2 * SCAN_B];
    __shared__ int boff_sh;
    int tid = threadIdx.x;
    int b = blockIdx.x;
    if (tid < 32) {
        int acc = 0;
        if (tid < b) acc += g_bsum[tid];
        if (32 + tid < b) acc += g_bsum[32 + tid];
#pragma unroll
        for (int o = 16; o > 0; o >>= 1) acc += __shfl_xor_sync(0xFFFFFFFFu, acc, o);
        if (tid == 0) boff_sh = acc;
    }
    int i = b * SCAN_B + tid;
    int v = (i < Nn) ? g_deg[i] : 0;
    sums[tid] = 0;
    sums[SCAN_B + tid] = v;
    __syncthreads();
    for (int off = 1; off < SCAN_B; off <<= 1) {
        int u = sums[SCAN_B + tid - off];
        __syncthreads();
        sums[SCAN_B + tid] += u;
        __syncthreads();
    }
    int excl = sums[SCAN_B - 1 + tid];       // exclusive within block
    int pref = boff_sh + excl;
    if (i < Nn) {
        g_rowptr[i] = pref;
        g_cursor[i] = pref;
    }
    if (b == nSB - 1 && tid == 0)
        g_rowptr[Nn] = boff_sh + sums[2 * SCAN_B - 1];
}

// ---------------- K2: scores1 blocks || scatter blocks -------------------------
__global__ __launch_bounds__(256)
void k2_scores1_scatter(const float* __restrict__ a1s, const float* __restrict__ a1d,
                        const void* __restrict__ ei, int Nn, int E, int nScoreBlocks) {
    if ((int)blockIdx.x < nScoreBlocks) {
        int idx = blockIdx.x * 256 + threadIdx.x;
        if (idx >= Nn * HEADS1) return;
        int n = idx >> 3, h = idx & 7;
        const float4* hp = (const float4*)(g_h1 + (size_t)n * H1DIM + h * 16);
        const float4* as = (const float4*)(a1s + h * 16);
        const float4* ad = (const float4*)(a1d + h * 16);
        float ss = 0.f, sd = 0.f;
#pragma unroll
        for (int q = 0; q < 4; q++) {
            float4 v = hp[q], s4 = as[q], d4 = ad[q];
            ss += v.x * s4.x + v.y * s4.y + v.z * s4.z + v.w * s4.w;
            sd += v.x * d4.x + v.y * d4.y + v.z * d4.z + v.w * d4.w;
        }
        g_s1src[idx] = ss;
        g_s1dst[idx] = sd;
    } else {
        int idx = (blockIdx.x - nScoreBlocks) * 256 + threadIdx.x;
        if (idx >= E + Nn) return;
        int src, dst;
        if (idx < E) {
            src = edge_at(ei, (size_t)idx);
            dst = edge_at(ei, (size_t)E + idx);
        } else {
            src = dst = idx - E;  // self loop
        }
        int pos = atomicAdd(&g_cursor[dst], 1);
        g_esrc[pos] = src;
    }
}

// ---------------- layer-1 softmax+agg (fp16 gather, coalesced esrc) -----------
__global__ __launch_bounds__(256)
void agg1_kernel(const float* __restrict__ b1, int Nn) {
    int warp = (blockIdx.x * blockDim.x + threadIdx.x) >> 5;
    int lane = threadIdx.x & 31;
    if (warp >= Nn) return;
    int beg = g_rowptr[warp], end = g_rowptr[warp + 1];
    const int head = lane >> 2;
    const float sdst = g_s1dst[(size_t)warp * HEADS1 + head];

    float4 acc = make_float4(0.f, 0.f, 0.f, 0.f);
    float s = 0.f;
    int j = beg;
    for (; j + 7 < end; j += 8) {
        // one coalesced load covers all 8 edge indices (1 sector)
        int eidx = g_esrc[j + (lane & 7)];
        int   idx[8];
        float w[8];
        uint2 u[8];
#pragma unroll
        for (int t = 0; t < 8; t++) idx[t] = __shfl_sync(0xFFFFFFFFu, eidx, t);
#pragma unroll
        for (int t = 0; t < 8; t++)
            u[t] = *(const uint2*)(g_h1h + (size_t)idx[t] * H1DIM + lane * 4);
#pragma unroll
        for (int t = 0; t < 8; t++)
            w[t] = __expf(lrelu(g_s1src[(size_t)idx[t] * HEADS1 + head] + sdst));
#pragma unroll
        for (int t = 0; t < 8; t++) {
            s += w[t];
            float2 p = __half22float2(*(__half2*)&u[t].x);
            float2 q = __half22float2(*(__half2*)&u[t].y);
            acc.x = fmaf(w[t], p.x, acc.x); acc.y = fmaf(w[t], p.y, acc.y);
            acc.z = fmaf(w[t], q.x, acc.z); acc.w = fmaf(w[t], q.y, acc.w);
        }
    }
    for (; j < end; ++j) {
        int i0 = g_esrc[j];
        float w0 = __expf(lrelu(g_s1src[(size_t)i0 * HEADS1 + head] + sdst));
        uint2 u0 = *(const uint2*)(g_h1h + (size_t)i0 * H1DIM + lane * 4);
        s += w0;
        float2 p = __half22float2(*(__half2*)&u0.x);
        float2 q = __half22float2(*(__half2*)&u0.y);
        acc.x = fmaf(w0, p.x, acc.x); acc.y = fmaf(w0, p.y, acc.y);
        acc.z = fmaf(w0, q.x, acc.z); acc.w = fmaf(w0, q.y, acc.w);
    }
    float inv = 1.0f / s;
    float4 bb = *(const float4*)(b1 + lane * 4);
    float4 o;
    o.x = acc.x * inv + bb.x;  o.y = acc.y * inv + bb.y;
    o.z = acc.z * inv + bb.z;  o.w = acc.w * inv + bb.w;
    o.x = (o.x > 0.f) ? o.x : (__expf(o.x) - 1.0f);
    o.y = (o.y > 0.f) ? o.y : (__expf(o.y) - 1.0f);
    o.z = (o.z > 0.f) ? o.z : (__expf(o.z) - 1.0f);
    o.w = (o.w > 0.f) ? o.w : (__expf(o.w) - 1.0f);
    *(float4*)(g_out1 + (size_t)warp * H1DIM + lane * 4) = o;
}

// ---------------- gemm2 (standalone) ------------------------------------------
__global__ __launch_bounds__(256)
void gemm2_kernel(const float* __restrict__ W2, int M) {
    gemm_body<H2DIM, 1>(nullptr, W2, M, H1DIM, blockIdx.x);
}

// ---------------- layer-2 scores (warp per node) -------------------------------
__global__ __launch_bounds__(256)
void scores2_kernel(const float* __restrict__ a2s, const float* __restrict__ a2d, int Nn) {
    int warp = (blockIdx.x * blockDim.x + threadIdx.x) >> 5;
    int lane = threadIdx.x & 31;
    if (warp >= Nn) return;
    const float2 v  = *(const float2*)(g_h2 + (size_t)warp * H2DIM + lane * 2);
    const float2 s2 = *(const float2*)(a2s + lane * 2);
    const float2 d2 = *(const float2*)(a2d + lane * 2);
    float ss = v.x * s2.x + v.y * s2.y;
    float sd = v.x * d2.x + v.y * d2.y;
#pragma unroll
    for (int o = 16; o > 0; o >>= 1) {
        ss += __shfl_xor_sync(0xFFFFFFFFu, ss, o);
        sd += __shfl_xor_sync(0xFFFFFFFFu, sd, o);
    }
    if (lane == 0) {
        g_s2src[warp] = ss;
        g_s2dst[warp] = sd;
    }
}

// ---------------- layer-2 softmax+agg (fp16 gather, coalesced esrc) -----------
__global__ __launch_bounds__(256)
void agg2_kernel(const float* __restrict__ b2, float* __restrict__ dout, int Nn) {
    int warp = (blockIdx.x * blockDim.x + threadIdx.x) >> 5;
    int lane = threadIdx.x & 31;
    if (warp >= Nn) return;
    int beg = g_rowptr[warp], end = g_rowptr[warp + 1];
    const float sdst = g_s2dst[warp];

    float a0 = 0.f, a1 = 0.f, s = 0.f;
    int j = beg;
    for (; j + 7 < end; j += 8) {
        int eidx = g_esrc[j + (lane & 7)];
        int     idx[8];
        float   w[8];
        __half2 u[8];
#pragma unroll
        for (int t = 0; t < 8; t++) idx[t] = __shfl_sync(0xFFFFFFFFu, eidx, t);
#pragma unroll
        for (int t = 0; t < 8; t++)
            u[t] = *(const __half2*)(g_h2h + (size_t)idx[t] * H2DIM + lane * 2);
#pragma unroll
        for (int t = 0; t < 8; t++)
            w[t] = __expf(lrelu(g_s2src[idx[t]] + sdst));
#pragma unroll
        for (int t = 0; t < 8; t++) {
            s += w[t];
            float2 f = __half22float2(u[t]);
            a0 = fmaf(w[t], f.x, a0); a1 = fmaf(w[t], f.y, a1);
        }
    }
    for (; j < end; ++j) {
        int i0 = g_esrc[j];
        float w0 = __expf(lrelu(g_s2src[i0] + sdst));
        __half2 u0 = *(const __half2*)(g_h2h + (size_t)i0 * H2DIM + lane * 2);
        s += w0;
        float2 f = __half22float2(u0);
        a0 = fmaf(w0, f.x, a0); a1 = fmaf(w0, f.y, a1);
    }
    float inv = 1.0f / s;
    float2 bb = *(const float2*)(b2 + lane * 2);
    float o0 = a0 * inv + bb.x;
    float o1 = a1 * inv + bb.y;

    float mx = fmaxf(o0, o1);
#pragma unroll
    for (int o = 16; o > 0; o >>= 1) mx = fmaxf(mx, __shfl_xor_sync(0xFFFFFFFFu, mx, o));
    float se = __expf(o0 - mx) + __expf(o1 - mx);
#pragma unroll
    for (int o = 16; o > 0; o >>= 1) se += __shfl_xor_sync(0xFFFFFFFFu, se, o);
    float lse = __logf(se);
    float2 r;  r.x = o0 - mx - lse;  r.y = o1 - mx - lse;
    *(float2*)(dout + (size_t)warp * H2DIM + lane * 2) = r;
}

// ---------------- launch (pure kernel launches, default stream) --------------
extern "C" void kernel_launch(void* const* d_in, const int* in_sizes, int n_in,
                              void* d_out, int out_size) {
    const float* x   = (const float*)d_in[0];
    const void*  ei  = d_in[1];
    const float* W1  = (const float*)d_in[2];
    const float* a1s = (const float*)d_in[3];
    const float* a1d = (const float*)d_in[4];
    const float* b1  = (const float*)d_in[5];
    const float* W2  = (const float*)d_in[6];
    const float* a2s = (const float*)d_in[7];
    const float* a2d = (const float*)d_in[8];
    const float* b2  = (const float*)d_in[9];
    float*       out = (float*)d_out;

    const int Nn   = in_sizes[0] / IN_DIM;  // 50000
    const int E    = in_sizes[1] / 2;       // 800000
    const int Etot = E + Nn;

    const int nG1 = (Nn + 127) / 128;             // gemm1 blocks
    const int nH  = (E + 255) / 256;              // histo blocks
    const int nS1 = (Nn * HEADS1 + 255) / 256;    // scores1 blocks
    const int nSc = (Etot + 255) / 256;           // scatter blocks
    const int nSB = (Nn + SCAN_B - 1) / SCAN_B;   // scan blocks (49)

    init_kernel<<<(Nn + 255) / 256, 256>>>((const int*)ei, Nn);
    k1_gemm1_histo<<<nG1 + nH, 256>>>(x, W1, ei, Nn, E, nG1);
    blocksum_kernel<<<nSB, SCAN_B>>>(Nn);
    final_scan_kernel<<<nSB, SCAN_B>>>(Nn, nSB);
    k2_scores1_scatter<<<nS1 + nSc, 256>>>(a1s, a1d, ei, Nn, E, nS1);
    agg1_kernel<<<(Nn + 7) / 8, 256>>>(b1, Nn);

    gemm2_kernel<<<(Nn + 127) / 128, 256>>>(W2, Nn);
    scores2_kernel<<<(Nn + 7) / 8, 256>>>(a2s, a2d, Nn);
    agg2_kernel<<<(Nn + 7) / 8, 256>>>(b2, out, Nn);
}